// round 13
// baseline (speedup 1.0000x reference)
#include <cuda_runtime.h>
#include <math.h>

// Problem constants
#define HH 768
#define WW 768
#define NIMG 32
#define HWI (768 * 768)
#define HWLL (768LL * 768LL)

#define TW 128                 // columns per warp strip
#define ROWS 16                // output rows per warp
#define KTOT 20                // rows loaded per warp (ROWS + 4 halo)
#define CHUNKS (HH / ROWS)     // 48 row-chunks
#define BLOCKS_X (WW / TW)     // 6
#define WPI (BLOCKS_X * CHUNKS)  // 288 warp-partials per image

#define MIN_WEIGHT 0.1f

__device__ float g_part[NIMG * WPI];   // fully rewritten every run

__device__ __forceinline__ float tanh_a(float x) {
    float r;
    asm("tanh.approx.f32 %0, %1;" : "=f"(r) : "f"(x));
    return r;
}
__device__ __forceinline__ float sigm(float x) {
    return fmaf(0.5f, tanh_a(0.5f * x), 0.5f);
}

// ---- load row (gi0 + kk - 2); INB folds away the guard at compile time ----
#define LOADROW(kk, INB, Y, H0, H1)                                             \
{                                                                               \
    const int gr = gi0 + (kk) - 2;                                              \
    Y = make_float4(0.f, 0.f, 0.f, 0.f); H0 = 0.f; H1 = 0.f;                    \
    if ((INB) || (unsigned)gr < (unsigned)HH) {                                 \
        Y = *reinterpret_cast<const float4*>(yimg + gr * WW + gj0);             \
        if (eL & hasL) {                                                        \
            float2 t = *reinterpret_cast<const float2*>(yimg + gr * WW + col0 - 2); \
            H0 = t.x; H1 = t.y;                                                 \
        }                                                                       \
        if (eR & hasR) {                                                        \
            float2 t = *reinterpret_cast<const float2*>(yimg + gr * WW + col0 + TW); \
            H0 = t.x; H1 = t.y;                                                 \
        }                                                                       \
    }                                                                           \
}

// ---- process row kk: sigmoid, shuffle halo, hs/hq, ring + running S/Q ----
#define PROCROW(kk, INB, Y, H0, H1)                                             \
{                                                                               \
    const int gr = gi0 + (kk) - 2;                                              \
    float4 p; float lz, lw, rx, ry;                                             \
    if ((INB) || (unsigned)gr < (unsigned)HH) {                                 \
        p.x = sigm(Y.x); p.y = sigm(Y.y); p.z = sigm(Y.z); p.w = sigm(Y.w);     \
        const float s0 = sigm(H0), s1 = sigm(H1);                               \
        lz = __shfl_up_sync(0xffffffffu, p.z, 1);                               \
        lw = __shfl_up_sync(0xffffffffu, p.w, 1);                               \
        rx = __shfl_down_sync(0xffffffffu, p.x, 1);                             \
        ry = __shfl_down_sync(0xffffffffu, p.y, 1);                             \
        if (eL) { lz = hasL ? s0 : 0.f; lw = hasL ? s1 : 0.f; }                 \
        if (eR) { rx = hasR ? s0 : 0.f; ry = hasR ? s1 : 0.f; }                 \
    } else {                                                                    \
        p = make_float4(0.f, 0.f, 0.f, 0.f); lz = lw = rx = ry = 0.f;           \
    }                                                                           \
    float4 hs, hq;                                                              \
    hs.x = lz + lw + p.x + p.y + p.z;                                           \
    hs.y = hs.x - lz + p.w;                                                     \
    hs.z = hs.y - lw + rx;                                                      \
    hs.w = hs.z - p.x + ry;                                                     \
    const float qlz = lz*lz, qlw = lw*lw, qx = p.x*p.x, qy = p.y*p.y;           \
    const float qz = p.z*p.z, qw = p.w*p.w, qrx = rx*rx, qry = ry*ry;           \
    hq.x = qlz + qlw + qx + qy + qz;                                            \
    hq.y = hq.x - qlz + qw;                                                     \
    hq.z = hq.y - qlw + qrx;                                                    \
    hq.w = hq.z - qx + qry;                                                     \
    S.x += hs.x - hsR[(kk) % 5].x;  S.y += hs.y - hsR[(kk) % 5].y;              \
    S.z += hs.z - hsR[(kk) % 5].z;  S.w += hs.w - hsR[(kk) % 5].w;              \
    Q.x += hq.x - hqR[(kk) % 5].x;  Q.y += hq.y - hqR[(kk) % 5].y;              \
    Q.z += hq.z - hqR[(kk) % 5].z;  Q.w += hq.w - hqR[(kk) % 5].w;              \
    hsR[(kk) % 5] = hs;  hqR[(kk) % 5] = hq;                                    \
    pR[(kk) % 3] = p;                                                           \
}

__global__ __launch_bounds__(128, 5) void k_pass1(
    const float* __restrict__ yd,
    const float* __restrict__ ygt,
    float* __restrict__ out)
{
    const int lane = threadIdx.x & 31;
    const int wrp  = threadIdx.x >> 5;
    const int img  = blockIdx.z;
    const int col0 = blockIdx.x * TW;
    const int chunk = blockIdx.y * 4 + wrp;      // 0..47
    const int gi0  = chunk * ROWS;               // first output row
    const int gj0  = col0 + lane * 4;

    const float* __restrict__ yimg = yd  + (long long)img * HWLL;
    const float* __restrict__ gimg = ygt + (long long)img * HWLL;
    float* __restrict__ oimg = out + (long long)img * HWLL;

    const bool eL = (lane == 0), eR = (lane == 31);
    const bool hasL = (col0 > 0), hasR = (col0 + TW < WW);

    float fcx[4], rinvI[4];
    #pragma unroll
    for (int m = 0; m < 4; ++m) {
        const int gj = gj0 + m;
        fcx[m]   = (float)(min(gj, 2) + min(WW - 1 - gj, 2) + 1);
        rinvI[m] = __fdividef(1.0f, fcx[m] * 5.0f - 1.0f);
    }

    float4 hsR[5], hqR[5], pR[3];
    #pragma unroll
    for (int i = 0; i < 5; ++i) {
        hsR[i] = make_float4(0.f, 0.f, 0.f, 0.f);
        hqR[i] = make_float4(0.f, 0.f, 0.f, 0.f);
    }
    float4 S = make_float4(0.f, 0.f, 0.f, 0.f);
    float4 Q = make_float4(0.f, 0.f, 0.f, 0.f);

    float lsum = 0.0f;

    float4 yc, yn; float hc0, hc1, hn0, hn1;
    LOADROW(0, false, yc, hc0, hc1)

    #pragma unroll
    for (int k = 0; k < KTOT; ++k) {
        // prefetch next y_d row (interior rows provably in bounds)
        if (k + 1 < KTOT) {
            LOADROW(k + 1, ((k + 1) >= 2) && ((k + 1) <= KTOT - 3), yn, hn0, hn1)
        }
        // issue y_gt load for this output row early (used at end of iteration)
        float4 gv;
        if (k >= 4)
            gv = *reinterpret_cast<const float4*>(gimg + (gi0 + k - 4) * WW + gj0);

        PROCROW(k, (k >= 2) && (k <= KTOT - 3), yc, hc0, hc1)

        if (k >= 4) {
            const int gro = gi0 + k - 4;
            const float4 P0 = pR[(k - 2) % 3];
            const bool  yin = (gro >= 2) & (gro < HH - 2);   // warp-uniform
            const float fcy = yin ? 5.0f
                                  : (float)(min(gro, 2) + min(HH - 1 - gro, 2) + 1);

            float4 w;
            #define DO_COMP(c, mi)                                              \
            {                                                                   \
                const float fnv  = fcx[mi] * fcy;                               \
                const float rinv = yin ? rinvI[mi]                              \
                                       : __fdividef(1.0f, fnv - 1.0f);          \
                const float p0  = P0.c;                                         \
                const float acc = fmaf(fmaf(fnv, p0, -2.0f * S.c), p0, Q.c);    \
                const float cons = 1.0f - acc * rinv;                           \
                const float qq  = 1.0f - p0;                                    \
                const float l2p = __log2f(fmaxf(p0, 1e-37f));                   \
                const float l2q = __log2f(fmaxf(qq, 1e-37f));                   \
                const float ent = fmaf(p0, l2p, fmaf(qq, l2q, 1.0f));           \
                float ww = fmaxf(cons * ent, gv.c);                             \
                w.c = fmaf(1.0f - MIN_WEIGHT, ww, MIN_WEIGHT);                  \
            }
            DO_COMP(x, 0)
            DO_COMP(y, 1)
            DO_COMP(z, 2)
            DO_COMP(w, 3)
            #undef DO_COMP

            *reinterpret_cast<float4*>(oimg + gro * WW + gj0) = w;
            lsum += (w.x + w.y) + (w.z + w.w);
        }

        yc = yn; hc0 = hn0; hc1 = hn1;
    }

    // ---- warp reduction -> one partial per warp (no smem, no barrier) ----
    #pragma unroll
    for (int o = 16; o; o >>= 1) lsum += __shfl_down_sync(0xffffffffu, lsum, o);
    if (lane == 0)
        g_part[img * WPI + chunk * BLOCKS_X + blockIdx.x] = lsum;
}

// in-place per-image normalization: out *= HW / sum[img]; 8 float4 per thread
__global__ __launch_bounds__(256) void k_pass2(float* __restrict__ out) {
    const int img = blockIdx.y;
    float4* p = reinterpret_cast<float4*>(out + (long long)img * HWLL);
    const int tid  = threadIdx.x;
    const int base = blockIdx.x * 2048 + tid;

    // issue all 8 loads first (MLP=8) so they fly during the reduction
    float4 v0 = p[base];
    float4 v1 = p[base + 256];
    float4 v2 = p[base + 512];
    float4 v3 = p[base + 768];
    float4 v4 = p[base + 1024];
    float4 v5 = p[base + 1280];
    float4 v6 = p[base + 1536];
    float4 v7 = p[base + 1792];

    __shared__ float s_scale;
    if (tid < 32) {
        float v = 0.0f;
        #pragma unroll
        for (int t = 0; t < 9; ++t) {
            const int idx = tid + t * 32;
            if (idx < WPI) v += g_part[img * WPI + idx];
        }
        #pragma unroll
        for (int o = 16; o; o >>= 1) v += __shfl_down_sync(0xffffffffu, v, o);
        if (tid == 0) s_scale = __fdividef((float)HWI, v);
    }
    __syncthreads();
    const float s = s_scale;

    #define SC(v) v.x *= s; v.y *= s; v.z *= s; v.w *= s;
    SC(v0) SC(v1) SC(v2) SC(v3) SC(v4) SC(v5) SC(v6) SC(v7)
    #undef SC
    p[base]        = v0;
    p[base + 256]  = v1;
    p[base + 512]  = v2;
    p[base + 768]  = v3;
    p[base + 1024] = v4;
    p[base + 1280] = v5;
    p[base + 1536] = v6;
    p[base + 1792] = v7;
}

extern "C" void kernel_launch(void* const* d_in, const int* in_sizes, int n_in,
                              void* d_out, int out_size) {
    const float* yd  = (const float*)d_in[0];
    const float* ygt = (const float*)d_in[1];
    float* out = (float*)d_out;

    dim3 b1(128);
    dim3 g1(BLOCKS_X, CHUNKS / 4, NIMG);    // (6, 12, 32) blocks of 4 warps
    k_pass1<<<g1, b1>>>(yd, ygt, out);

    dim3 g2(HWI / 4 / 2048, NIMG);          // (72, 32)
    k_pass2<<<g2, 256>>>(out);
}

// round 14
// speedup vs baseline: 1.1287x; 1.1287x over previous
#include <cuda_runtime.h>
#include <math.h>

// Problem constants
#define HH 768
#define WW 768
#define NIMG 32
#define HWI (768 * 768)
#define HWLL (768LL * 768LL)

#define TW 128                 // columns per warp strip
#define ROWS 16                // output rows per warp
#define KTOT 20                // rows loaded per warp (ROWS + 4 halo)
#define CHUNKS (HH / ROWS)     // 48 row-chunks
#define BLOCKS_X (WW / TW)     // 6
#define WPI (BLOCKS_X * CHUNKS)  // 288 warp-partials per image

#define MIN_WEIGHT 0.1f
#define INV_LOG2 1.4426950408889634f

__device__ float g_part[NIMG * WPI];   // fully rewritten every run

__device__ __forceinline__ float tanh_a(float x) {
    float r;
    asm("tanh.approx.f32 %0, %1;" : "=f"(r) : "f"(x));
    return r;
}
__device__ __forceinline__ float sigm(float x) {
    return fmaf(0.5f, tanh_a(0.5f * x), 0.5f);
}

// ---- load row (gi0 + kk - 2); INB folds away the guard at compile time ----
#define LOADROW(kk, INB, Y, H0, H1)                                             \
{                                                                               \
    const int gr = gi0 + (kk) - 2;                                              \
    Y = make_float4(0.f, 0.f, 0.f, 0.f); H0 = 0.f; H1 = 0.f;                    \
    if ((INB) || (unsigned)gr < (unsigned)HH) {                                 \
        Y = *reinterpret_cast<const float4*>(yimg + gr * WW + gj0);             \
        if (eL & hasL) {                                                        \
            float2 t = *reinterpret_cast<const float2*>(yimg + gr * WW + col0 - 2); \
            H0 = t.x; H1 = t.y;                                                 \
        }                                                                       \
        if (eR & hasR) {                                                        \
            float2 t = *reinterpret_cast<const float2*>(yimg + gr * WW + col0 + TW); \
            H0 = t.x; H1 = t.y;                                                 \
        }                                                                       \
    }                                                                           \
}

// ---- process row kk: sigmoid, shuffle halo, hs/hq, rings + running S/Q ----
#define PROCROW(kk, INB, Y, H0, H1)                                             \
{                                                                               \
    const int gr = gi0 + (kk) - 2;                                              \
    float4 p; float lz, lw, rx, ry;                                             \
    if ((INB) || (unsigned)gr < (unsigned)HH) {                                 \
        p.x = sigm(Y.x); p.y = sigm(Y.y); p.z = sigm(Y.z); p.w = sigm(Y.w);     \
        const float s0 = sigm(H0), s1 = sigm(H1);                               \
        lz = __shfl_up_sync(0xffffffffu, p.z, 1);                               \
        lw = __shfl_up_sync(0xffffffffu, p.w, 1);                               \
        rx = __shfl_down_sync(0xffffffffu, p.x, 1);                             \
        ry = __shfl_down_sync(0xffffffffu, p.y, 1);                             \
        if (eL) { lz = hasL ? s0 : 0.f; lw = hasL ? s1 : 0.f; }                 \
        if (eR) { rx = hasR ? s0 : 0.f; ry = hasR ? s1 : 0.f; }                 \
    } else {                                                                    \
        p = make_float4(0.f, 0.f, 0.f, 0.f); lz = lw = rx = ry = 0.f;           \
    }                                                                           \
    float4 hs, hq;                                                              \
    hs.x = lz + lw + p.x + p.y + p.z;                                           \
    hs.y = hs.x - lz + p.w;                                                     \
    hs.z = hs.y - lw + rx;                                                      \
    hs.w = hs.z - p.x + ry;                                                     \
    const float qlz = lz*lz, qlw = lw*lw, qx = p.x*p.x, qy = p.y*p.y;           \
    const float qz = p.z*p.z, qw = p.w*p.w, qrx = rx*rx, qry = ry*ry;           \
    hq.x = qlz + qlw + qx + qy + qz;                                            \
    hq.y = hq.x - qlz + qw;                                                     \
    hq.z = hq.y - qlw + qrx;                                                    \
    hq.w = hq.z - qx + qry;                                                     \
    S.x += hs.x - hsR[(kk) % 5].x;  S.y += hs.y - hsR[(kk) % 5].y;              \
    S.z += hs.z - hsR[(kk) % 5].z;  S.w += hs.w - hsR[(kk) % 5].w;              \
    Q.x += hq.x - hqR[(kk) % 5].x;  Q.y += hq.y - hqR[(kk) % 5].y;              \
    Q.z += hq.z - hqR[(kk) % 5].z;  Q.w += hq.w - hqR[(kk) % 5].w;              \
    hsR[(kk) % 5] = hs;  hqR[(kk) % 5] = hq;                                    \
    pR[(kk) % 3] = p;  yR[(kk) % 3] = Y;                                        \
}

__global__ __launch_bounds__(128, 4) void k_pass1(
    const float* __restrict__ yd,
    const float* __restrict__ ygt,
    float* __restrict__ out)
{
    const int lane = threadIdx.x & 31;
    const int wrp  = threadIdx.x >> 5;
    const int img  = blockIdx.z;
    const int col0 = blockIdx.x * TW;
    const int chunk = blockIdx.y * 4 + wrp;      // 0..47
    const int gi0  = chunk * ROWS;               // first output row
    const int gj0  = col0 + lane * 4;

    const float* __restrict__ yimg = yd  + (long long)img * HWLL;
    const float* __restrict__ gimg = ygt + (long long)img * HWLL;
    float* __restrict__ oimg = out + (long long)img * HWLL;

    const bool eL = (lane == 0), eR = (lane == 31);
    const bool hasL = (col0 > 0), hasR = (col0 + TW < WW);

    float fcx[4], rinvI[4];
    #pragma unroll
    for (int m = 0; m < 4; ++m) {
        const int gj = gj0 + m;
        fcx[m]   = (float)(min(gj, 2) + min(WW - 1 - gj, 2) + 1);
        rinvI[m] = __fdividef(1.0f, fcx[m] * 5.0f - 1.0f);
    }

    float4 hsR[5], hqR[5], pR[3], yR[3];
    #pragma unroll
    for (int i = 0; i < 5; ++i) {
        hsR[i] = make_float4(0.f, 0.f, 0.f, 0.f);
        hqR[i] = make_float4(0.f, 0.f, 0.f, 0.f);
    }
    float4 S = make_float4(0.f, 0.f, 0.f, 0.f);
    float4 Q = make_float4(0.f, 0.f, 0.f, 0.f);

    float lsum = 0.0f;

    float4 yc, yn; float hc0, hc1, hn0, hn1;
    LOADROW(0, false, yc, hc0, hc1)

    #pragma unroll
    for (int k = 0; k < KTOT; ++k) {
        // prefetch next y_d row (interior rows provably in bounds)
        if (k + 1 < KTOT) {
            LOADROW(k + 1, ((k + 1) >= 2) && ((k + 1) <= KTOT - 3), yn, hn0, hn1)
        }
        // issue y_gt load for this output row early
        float4 gv;
        if (k >= 4)
            gv = *reinterpret_cast<const float4*>(gimg + (gi0 + k - 4) * WW + gj0);

        PROCROW(k, (k >= 2) && (k <= KTOT - 3), yc, hc0, hc1)

        if (k >= 4) {
            const int gro = gi0 + k - 4;
            const float4 P0 = pR[(k - 2) % 3];   // center-row p
            const float4 Y0 = yR[(k - 2) % 3];   // center-row y (pre-sigmoid)
            const bool  yin = (gro >= 2) & (gro < HH - 2);   // warp-uniform
            const float fcy = yin ? 5.0f
                                  : (float)(min(gro, 2) + min(HH - 1 - gro, 2) + 1);

            float4 w;
            // entropy identity: 1 + p*l2(p) + q*l2(q)
            //   = 1 + 0.5*l2(p*q) + 0.5*(p-q)*y*log2(e)      (since p/q = e^y)
            #define DO_COMP(c, mi)                                              \
            {                                                                   \
                const float fnv  = fcx[mi] * fcy;                               \
                const float rinv = yin ? rinvI[mi]                              \
                                       : __fdividef(1.0f, fnv - 1.0f);          \
                const float p0  = P0.c;                                         \
                const float acc = fmaf(fmaf(fnv, p0, -2.0f * S.c), p0, Q.c);    \
                const float cons = 1.0f - acc * rinv;                           \
                const float qq  = 1.0f - p0;                                    \
                const float pq  = fmaxf(p0 * qq, 1e-37f);                       \
                const float l2  = __log2f(pq);                                  \
                const float tt  = p0 - qq;                                      \
                const float ent = fmaf(0.5f, l2,                                \
                                   fmaf((0.5f * INV_LOG2) * tt, Y0.c, 1.0f));   \
                float ww = fmaxf(cons * ent, gv.c);                             \
                w.c = fmaf(1.0f - MIN_WEIGHT, ww, MIN_WEIGHT);                  \
            }
            DO_COMP(x, 0)
            DO_COMP(y, 1)
            DO_COMP(z, 2)
            DO_COMP(w, 3)
            #undef DO_COMP

            *reinterpret_cast<float4*>(oimg + gro * WW + gj0) = w;
            lsum += (w.x + w.y) + (w.z + w.w);
        }

        yc = yn; hc0 = hn0; hc1 = hn1;
    }

    // ---- warp reduction -> one partial per warp (no smem, no barrier) ----
    #pragma unroll
    for (int o = 16; o; o >>= 1) lsum += __shfl_down_sync(0xffffffffu, lsum, o);
    if (lane == 0)
        g_part[img * WPI + chunk * BLOCKS_X + blockIdx.x] = lsum;
}

// in-place per-image normalization: out *= HW / sum[img]; 8 float4 per thread
__global__ __launch_bounds__(256) void k_pass2(float* __restrict__ out) {
    const int img = blockIdx.y;
    float4* p = reinterpret_cast<float4*>(out + (long long)img * HWLL);
    const int tid  = threadIdx.x;
    const int base = blockIdx.x * 2048 + tid;

    // issue all 8 loads first (MLP=8) so they fly during the reduction
    float4 v0 = p[base];
    float4 v1 = p[base + 256];
    float4 v2 = p[base + 512];
    float4 v3 = p[base + 768];
    float4 v4 = p[base + 1024];
    float4 v5 = p[base + 1280];
    float4 v6 = p[base + 1536];
    float4 v7 = p[base + 1792];

    __shared__ float s_scale;
    if (tid < 32) {
        float v = 0.0f;
        #pragma unroll
        for (int t = 0; t < 9; ++t) {
            const int idx = tid + t * 32;
            if (idx < WPI) v += g_part[img * WPI + idx];
        }
        #pragma unroll
        for (int o = 16; o; o >>= 1) v += __shfl_down_sync(0xffffffffu, v, o);
        if (tid == 0) s_scale = __fdividef((float)HWI, v);
    }
    __syncthreads();
    const float s = s_scale;

    #define SC(v) v.x *= s; v.y *= s; v.z *= s; v.w *= s;
    SC(v0) SC(v1) SC(v2) SC(v3) SC(v4) SC(v5) SC(v6) SC(v7)
    #undef SC
    p[base]        = v0;
    p[base + 256]  = v1;
    p[base + 512]  = v2;
    p[base + 768]  = v3;
    p[base + 1024] = v4;
    p[base + 1280] = v5;
    p[base + 1536] = v6;
    p[base + 1792] = v7;
}

extern "C" void kernel_launch(void* const* d_in, const int* in_sizes, int n_in,
                              void* d_out, int out_size) {
    const float* yd  = (const float*)d_in[0];
    const float* ygt = (const float*)d_in[1];
    float* out = (float*)d_out;

    dim3 b1(128);
    dim3 g1(BLOCKS_X, CHUNKS / 4, NIMG);    // (6, 12, 32) blocks of 4 warps
    k_pass1<<<g1, b1>>>(yd, ygt, out);

    dim3 g2(HWI / 4 / 2048, NIMG);          // (72, 32)
    k_pass2<<<g2, 256>>>(out);
}

// round 15
// speedup vs baseline: 1.1739x; 1.0401x over previous
#include <cuda_runtime.h>
#include <math.h>

// Problem constants
#define HH 768
#define WW 768
#define NIMG 32
#define HWI (768 * 768)
#define HWLL (768LL * 768LL)

#define TW 128                 // columns per warp strip
#define ROWS 16                // output rows per warp
#define KTOT 20                // rows loaded per warp (ROWS + 4 halo)
#define CHUNKS (HH / ROWS)     // 48 row-chunks
#define BLOCKS_X (WW / TW)     // 6
#define BLOCKS_Y (CHUNKS / 4)  // 12 (4 warps per block)
#define BPI (BLOCKS_X * BLOCKS_Y)  // 72 block-partials per image

#define MIN_WEIGHT 0.1f

__device__ float g_part[NIMG * BPI];   // fully rewritten every run
__device__ int   g_cnt[NIMG];          // monotonic epoch counters (never reset)

__device__ __forceinline__ float tanh_a(float x) {
    float r;
    asm("tanh.approx.f32 %0, %1;" : "=f"(r) : "f"(x));
    return r;
}
__device__ __forceinline__ float sigm(float x) {
    return fmaf(0.5f, tanh_a(0.5f * x), 0.5f);
}

// ---- load row (gi0 + kk - 2); INB folds away the guard at compile time ----
#define LOADROW(kk, INB, Y, H0, H1)                                             \
{                                                                               \
    const int gr = gi0 + (kk) - 2;                                              \
    Y = make_float4(0.f, 0.f, 0.f, 0.f); H0 = 0.f; H1 = 0.f;                    \
    if ((INB) || (unsigned)gr < (unsigned)HH) {                                 \
        Y = *reinterpret_cast<const float4*>(yimg + gr * WW + gj0);             \
        if (eL & hasL) {                                                        \
            float2 t = *reinterpret_cast<const float2*>(yimg + gr * WW + col0 - 2); \
            H0 = t.x; H1 = t.y;                                                 \
        }                                                                       \
        if (eR & hasR) {                                                        \
            float2 t = *reinterpret_cast<const float2*>(yimg + gr * WW + col0 + TW); \
            H0 = t.x; H1 = t.y;                                                 \
        }                                                                       \
    }                                                                           \
}

// ---- process row kk: sigmoid, shuffle halo, hs/hq, rings + running S/Q ----
#define PROCROW(kk, INB, Y, H0, H1)                                             \
{                                                                               \
    const int gr = gi0 + (kk) - 2;                                              \
    float4 p; float lz, lw, rx, ry;                                             \
    if ((INB) || (unsigned)gr < (unsigned)HH) {                                 \
        p.x = sigm(Y.x); p.y = sigm(Y.y); p.z = sigm(Y.z); p.w = sigm(Y.w);     \
        const float s0 = sigm(H0), s1 = sigm(H1);                               \
        lz = __shfl_up_sync(0xffffffffu, p.z, 1);                               \
        lw = __shfl_up_sync(0xffffffffu, p.w, 1);                               \
        rx = __shfl_down_sync(0xffffffffu, p.x, 1);                             \
        ry = __shfl_down_sync(0xffffffffu, p.y, 1);                             \
        if (eL) { lz = hasL ? s0 : 0.f; lw = hasL ? s1 : 0.f; }                 \
        if (eR) { rx = hasR ? s0 : 0.f; ry = hasR ? s1 : 0.f; }                 \
    } else {                                                                    \
        p = make_float4(0.f, 0.f, 0.f, 0.f); lz = lw = rx = ry = 0.f;           \
    }                                                                           \
    float4 hs, hq;                                                              \
    hs.x = lz + lw + p.x + p.y + p.z;                                           \
    hs.y = hs.x - lz + p.w;                                                     \
    hs.z = hs.y - lw + rx;                                                      \
    hs.w = hs.z - p.x + ry;                                                     \
    const float qlz = lz*lz, qlw = lw*lw, qx = p.x*p.x, qy = p.y*p.y;           \
    const float qz = p.z*p.z, qw = p.w*p.w, qrx = rx*rx, qry = ry*ry;           \
    hq.x = qlz + qlw + qx + qy + qz;                                            \
    hq.y = hq.x - qlz + qw;                                                     \
    hq.z = hq.y - qlw + qrx;                                                    \
    hq.w = hq.z - qx + qry;                                                     \
    S.x += hs.x - hsR[(kk) % 5].x;  S.y += hs.y - hsR[(kk) % 5].y;              \
    S.z += hs.z - hsR[(kk) % 5].z;  S.w += hs.w - hsR[(kk) % 5].w;              \
    Q.x += hq.x - hqR[(kk) % 5].x;  Q.y += hq.y - hqR[(kk) % 5].y;              \
    Q.z += hq.z - hqR[(kk) % 5].z;  Q.w += hq.w - hqR[(kk) % 5].w;              \
    hsR[(kk) % 5] = hs;  hqR[(kk) % 5] = hq;                                    \
    pR[(kk) % 3] = p;                                                           \
}

__global__ __launch_bounds__(128, 4) void k_fused(
    const float* __restrict__ yd,
    const float* __restrict__ ygt,
    float* __restrict__ out)
{
    // per-warp stash: 16 rows x 128 cols fp32 = 8 KB/warp, 32 KB/CTA
    __shared__ float stash[4 * ROWS * TW];
    __shared__ float wsum[4];
    __shared__ float s_scale;

    const int lane = threadIdx.x & 31;
    const int wrp  = threadIdx.x >> 5;
    const int tid  = threadIdx.x;
    const int img  = blockIdx.z;
    const int col0 = blockIdx.x * TW;
    const int chunk = blockIdx.y * 4 + wrp;      // 0..47
    const int gi0  = chunk * ROWS;               // first output row
    const int gj0  = col0 + lane * 4;

    const float* __restrict__ yimg = yd  + (long long)img * HWLL;
    const float* __restrict__ gimg = ygt + (long long)img * HWLL;
    float* __restrict__ oimg = out + (long long)img * HWLL;

    const bool eL = (lane == 0), eR = (lane == 31);
    const bool hasL = (col0 > 0), hasR = (col0 + TW < WW);

    float fcx[4], rinvI[4];
    #pragma unroll
    for (int m = 0; m < 4; ++m) {
        const int gj = gj0 + m;
        fcx[m]   = (float)(min(gj, 2) + min(WW - 1 - gj, 2) + 1);
        rinvI[m] = __fdividef(1.0f, fcx[m] * 5.0f - 1.0f);
    }

    float4 hsR[5], hqR[5], pR[3];
    #pragma unroll
    for (int i = 0; i < 5; ++i) {
        hsR[i] = make_float4(0.f, 0.f, 0.f, 0.f);
        hqR[i] = make_float4(0.f, 0.f, 0.f, 0.f);
    }
    float4 S = make_float4(0.f, 0.f, 0.f, 0.f);
    float4 Q = make_float4(0.f, 0.f, 0.f, 0.f);

    float lsum = 0.0f;

    float4 yc, yn; float hc0, hc1, hn0, hn1;
    LOADROW(0, false, yc, hc0, hc1)

    float* mystash = stash + (wrp * ROWS) * TW;

    #pragma unroll
    for (int k = 0; k < KTOT; ++k) {
        if (k + 1 < KTOT) {
            LOADROW(k + 1, ((k + 1) >= 2) && ((k + 1) <= KTOT - 3), yn, hn0, hn1)
        }
        float4 gv;
        if (k >= 4)
            gv = *reinterpret_cast<const float4*>(gimg + (gi0 + k - 4) * WW + gj0);

        PROCROW(k, (k >= 2) && (k <= KTOT - 3), yc, hc0, hc1)

        if (k >= 4) {
            const int gro = gi0 + k - 4;
            const float4 P0 = pR[(k - 2) % 3];
            const bool  yin = (gro >= 2) & (gro < HH - 2);   // warp-uniform
            const float fcy = yin ? 5.0f
                                  : (float)(min(gro, 2) + min(HH - 1 - gro, 2) + 1);

            float4 w;
            #define DO_COMP(c, mi)                                              \
            {                                                                   \
                const float fnv  = fcx[mi] * fcy;                               \
                const float rinv = yin ? rinvI[mi]                              \
                                       : __fdividef(1.0f, fnv - 1.0f);          \
                const float p0  = P0.c;                                         \
                const float acc = fmaf(fmaf(fnv, p0, -2.0f * S.c), p0, Q.c);    \
                const float cons = 1.0f - acc * rinv;                           \
                const float qq  = 1.0f - p0;                                    \
                const float l2p = __log2f(fmaxf(p0, 1e-37f));                   \
                const float l2q = __log2f(fmaxf(qq, 1e-37f));                   \
                const float ent = fmaf(p0, l2p, fmaf(qq, l2q, 1.0f));           \
                float ww = fmaxf(cons * ent, gv.c);                             \
                w.c = fmaf(1.0f - MIN_WEIGHT, ww, MIN_WEIGHT);                  \
            }
            DO_COMP(x, 0)
            DO_COMP(y, 1)
            DO_COMP(z, 2)
            DO_COMP(w, 3)
            #undef DO_COMP

            // stash unscaled w in smem (conflict-free STS.128)
            *reinterpret_cast<float4*>(mystash + (k - 4) * TW + lane * 4) = w;
            lsum += (w.x + w.y) + (w.z + w.w);
        }

        yc = yn; hc0 = hn0; hc1 = hn1;
    }

    // ---- warp reduce -> block partial ----
    #pragma unroll
    for (int o = 16; o; o >>= 1) lsum += __shfl_down_sync(0xffffffffu, lsum, o);
    if (lane == 0) wsum[wrp] = lsum;
    __syncthreads();

    // ---- publish partial, monotonic epoch spin until image complete ----
    if (tid == 0) {
        float v = wsum[0] + wsum[1] + wsum[2] + wsum[3];
        g_part[img * BPI + blockIdx.y * BLOCKS_X + blockIdx.x] = v;
        __threadfence();
        const int t0 = atomicAdd(&g_cnt[img], 1);
        const int target = t0 - (t0 % BPI) + BPI;   // epoch end (monotonic)
        volatile int* c = &g_cnt[img];
        while (*c < target) __nanosleep(100);
        __threadfence();
    }
    __syncthreads();

    // ---- reduce the 72 partials, compute scale ----
    if (tid < 32) {
        float v = 0.0f;
        #pragma unroll
        for (int t = 0; t < 3; ++t) {
            const int idx = tid + t * 32;
            if (idx < BPI) v += g_part[img * BPI + idx];
        }
        #pragma unroll
        for (int o = 16; o; o >>= 1) v += __shfl_down_sync(0xffffffffu, v, o);
        if (tid == 0) s_scale = __fdividef((float)HWI, v);
    }
    __syncthreads();
    const float s = s_scale;

    // ---- scaled store: the ONLY global write of out ----
    #pragma unroll
    for (int o = 0; o < ROWS; ++o) {
        float4 w = *reinterpret_cast<const float4*>(mystash + o * TW + lane * 4);
        w.x *= s; w.y *= s; w.z *= s; w.w *= s;
        *reinterpret_cast<float4*>(oimg + (gi0 + o) * WW + gj0) = w;
    }
}

extern "C" void kernel_launch(void* const* d_in, const int* in_sizes, int n_in,
                              void* d_out, int out_size) {
    const float* yd  = (const float*)d_in[0];
    const float* ygt = (const float*)d_in[1];
    float* out = (float*)d_out;

    dim3 b1(128);
    dim3 g1(BLOCKS_X, BLOCKS_Y, NIMG);      // (6, 12, 32)
    k_fused<<<g1, b1>>>(yd, ygt, out);
}